// round 7
// baseline (speedup 1.0000x reference)
#include <cuda_runtime.h>
#include <cuda_fp16.h>
#include <cstdint>

// ---------------- problem constants ----------------
#define OUTF  11008
#define INF   4096
#define BATCH 64
#define NG    32            // 4096/128 quant groups
#define MTILE 128           // weight rows per CTA
#define KC    64            // K per chunk
#define NCHUNK 64           // 4096/64
#define NBLK  (OUTF / MTILE)   // 86 CTAs

// X ring: 5 slots, prefetch distance 3 (slot overwritten 2 iters after last read)
#define NX    5
#define SPREF 3

// smem layout from 1KB-aligned base:
//   [0, 8K)        scales (128 rows x 32 groups fp16)
//   [8K, 48K)      X ring: 5 x 8KB
//   [48K, 80K)     Wfp double buffer: 2 x 16KB
#define SMEM_GEMM (8192 + NX * 8192 + 2 * 16384 + 1024)   // 82944

// ---------------- device globals ----------------
__device__ __half2 g_x16[BATCH * INF / 2];
__device__ __half  g_sc16[OUTF * NG];
__device__ float   g_badd[OUTF];

// ---------------- helpers ----------------
static __device__ __forceinline__ uint32_t smem_u32(const void* p) {
    uint32_t a;
    asm("{ .reg .u64 t; cvta.to.shared.u64 t, %1; cvt.u32.u64 %0, t; }" : "=r"(a) : "l"(p));
    return a;
}
static __device__ __forceinline__ uint32_t swz(uint32_t off) {
    return off ^ ((off >> 3) & 0x70);
}
static __device__ __forceinline__ void cpa16(uint32_t dst, const void* src) {
    asm volatile("cp.async.cg.shared.global [%0], [%1], 16;" :: "r"(dst), "l"(src));
}
static __device__ __forceinline__ void cpa_commit() {
    asm volatile("cp.async.commit_group;" ::: "memory");
}
static __device__ __forceinline__ void ldsm4(uint32_t* r, uint32_t addr) {
    asm volatile("ldmatrix.sync.aligned.m8n8.x4.shared.b16 {%0,%1,%2,%3}, [%4];"
        : "=r"(r[0]), "=r"(r[1]), "=r"(r[2]), "=r"(r[3]) : "r"(addr));
}
static __device__ __forceinline__ void mma16816(float* d, const uint32_t* a,
                                                uint32_t b0, uint32_t b1) {
    asm volatile("mma.sync.aligned.m16n8k16.row.col.f32.f16.f16.f32 "
        "{%0,%1,%2,%3}, {%4,%5,%6,%7}, {%8,%9}, {%0,%1,%2,%3};"
        : "+f"(d[0]), "+f"(d[1]), "+f"(d[2]), "+f"(d[3])
        : "r"(a[0]), "r"(a[1]), "r"(a[2]), "r"(a[3]), "r"(b0), "r"(b1));
}
static __device__ __forceinline__ __half2 u32_as_h2(uint32_t u) {
    __half2 h; *reinterpret_cast<uint32_t*>(&h) = u; return h;
}
static __device__ __forceinline__ uint32_t h2_as_u32(__half2 h) {
    return *reinterpret_cast<uint32_t*>(&h);
}

#define STS128(addr, r0, r1, r2, r3) \
    asm volatile("st.shared.v4.b32 [%0], {%1, %2, %3, %4};" \
        :: "r"(addr), "r"(r0), "r"(r1), "r"(r2), "r"(r3) : "memory")

// 4 int8 bytes (packed u32) -> 2 half2, times s2 (exact: PRMT 0x6400 trick)
static __device__ __forceinline__ void dq4(uint32_t packed, __half2 s2, __half2 c1152,
                                           uint32_t& o0, uint32_t& o1) {
    uint32_t v  = packed ^ 0x80808080u;
    uint32_t lo = __byte_perm(v, 0x64646464u, 0x4140);
    uint32_t hi = __byte_perm(v, 0x64646464u, 0x4342);
    o0 = h2_as_u32(__hmul2(__hsub2(u32_as_h2(lo), c1152), s2));
    o1 = h2_as_u32(__hmul2(__hsub2(u32_as_h2(hi), c1152), s2));
}

static __device__ __forceinline__ float read_mode16(const void* p, int i, int mode) {
    if (mode == 1) {                       // bf16
        unsigned short u = reinterpret_cast<const unsigned short*>(p)[i];
        return __uint_as_float(((unsigned)u) << 16);
    } else if (mode == 0) {                // fp16
        return __half2float(reinterpret_cast<const __half*>(p)[i]);
    }
    return reinterpret_cast<const float*>(p)[i];   // f32
}

// ---------------- fused prolog: x->fp16, scale->fp16, bias+res->f32 ----------------
__global__ void prolog_kernel(const float* __restrict__ x,
                              const void* __restrict__ s,
                              const void* __restrict__ b,
                              const void* __restrict__ r) {
    const int idx = blockIdx.x * 256 + threadIdx.x;   // 512*256 = 131072

    // x: one half2 per thread
    float2 v = reinterpret_cast<const float2*>(x)[idx];
    g_x16[idx] = __floats2half2_rn(v.x, v.y);

    // per-block scale dtype detection (256B, L2-resident, uniform result)
    bool bf = true, fh = true;
    const unsigned* su = (const unsigned*)s;
    #pragma unroll 8
    for (int i = 0; i < 64; i++) {
        unsigned w = su[i];
        #pragma unroll
        for (int h = 0; h < 2; h++) {
            unsigned u = (h ? (w >> 16) : w) & 0xFFFFu;
            float ab = __uint_as_float(u << 16);
            float af = __half2float(__ushort_as_half((unsigned short)u));
            bf &= (ab > 5e-5f && ab < 0.02f);
            fh &= (af > 5e-5f && af < 0.02f);
        }
    }
    const int m = bf ? 1 : (fh ? 0 : 2);

    for (int i = idx; i < OUTF * NG; i += 512 * 256)
        g_sc16[i] = __float2half(read_mode16(s, i, m));
    if (idx < OUTF)
        g_badd[idx] = read_mode16(b, idx, m) + read_mode16(r, idx, m);
}

// ---------------- unified GEMM body (WMODE: 1 = int32 weights, 0 = int8) --------
template <int WMODE>
static __device__ __forceinline__ void gemm_body(const char* __restrict__ Wb,
                                                 float* __restrict__ out) {
    extern __shared__ char smem_raw[];
    uint32_t sb = (smem_u32(smem_raw) + 1023) & ~1023u;
    const int tid = threadIdx.x, lane = tid & 31, wid = tid >> 5;
    const int mr = wid & 3, nc = wid >> 2;
    const int t = lane >> 3;
    const int row0 = blockIdx.x * MTILE;
    const char* xb = (const char*)g_x16;
    const uint32_t SC = sb, X0 = sb + 8192, WFP = sb + 8192 + NX * 8192;

    // W ownership: thread -> row rr, column-half hh (32 values per chunk)
    const int rr = tid >> 1, hh = tid & 1;
    const char* wbase = Wb + ((size_t)(row0 + rr) * INF + hh * 32) * (WMODE ? 4 : 1);

    auto issueX = [&](int p, int slot) {
        uint32_t xsl = X0 + slot * 8192;
        const int k0 = p * KC;
        #pragma unroll
        for (int j = 0; j < 2; j++) {
            int c = tid + j * 256, r = c >> 3, q = c & 7;
            cpa16(xsl + swz(r * 128 + q * 16),
                  xb + (size_t)r * (INF * 2) + (size_t)k0 * 2 + q * 16);
        }
    };

    int4 wreg[WMODE ? 8 : 2];
    auto loadW = [&](int p) {
        const int4* src = (const int4*)(wbase + (size_t)p * KC * (WMODE ? 4 : 1));
        #pragma unroll
        for (int j = 0; j < (WMODE ? 8 : 2); j++) wreg[j] = __ldg(src + j);
    };

    {   // prologue: scales + 3 X chunks + W chunk 0
        const char* scb = (const char*)g_sc16 + (size_t)row0 * NG * 2;
        #pragma unroll
        for (int j = 0; j < 2; j++) {
            int c = tid + j * 256;
            cpa16(SC + c * 16, scb + c * 16);
        }
        issueX(0, 0); cpa_commit();
        issueX(1, 1); cpa_commit();
        issueX(2, 2); cpa_commit();
        loadW(0);
    }

    const __half2 c1152 = __half2half2(__ushort_as_half((unsigned short)0x6480));
    float acc[2][4][4] = {};
    int rd = 0, wr = SPREF;

    for (int i = 0; i < NCHUNK; i++) {
        asm volatile("cp.async.wait_group %0;" :: "n"(SPREF - 1) : "memory");
        __syncthreads();                         // X chunk i + scales visible

        const uint32_t xsl = X0 + rd * 8192;
        const uint32_t wfp = WFP + (i & 1) * 16384;

        // ---- B fragments from X ----
        uint32_t bfr[4][8];
        #pragma unroll
        for (int kt = 0; kt < 4; kt++)
            #pragma unroll
            for (int np = 0; np < 2; np++) {
                int n  = nc * 32 + np * 16 + ((t >> 1) << 3) + (lane & 7);
                int cb = kt * 32 + ((t & 1) << 4);
                ldsm4(&bfr[kt][np * 4], xsl + swz(n * 128 + cb));
            }

        // ---- dequant W regs -> Wfp smem ----
        {
            const int g = i >> 1;
            unsigned short sv;
            asm volatile("ld.shared.u16 %0, [%1];" : "=h"(sv)
                : "r"(SC + (uint32_t)(rr * NG + g) * 2) : "memory");
            __half2 s2 = __half2half2(__ushort_as_half(sv));
            uint32_t o[16];
            if (WMODE) {
                #pragma unroll
                for (int j = 0; j < 8; j++) {
                    uint32_t t01 = __byte_perm((uint32_t)wreg[j].x, (uint32_t)wreg[j].y, 0x0040);
                    uint32_t t23 = __byte_perm((uint32_t)wreg[j].z, (uint32_t)wreg[j].w, 0x0040);
                    uint32_t pk  = __byte_perm(t01, t23, 0x5410);
                    dq4(pk, s2, c1152, o[2 * j], o[2 * j + 1]);
                }
            } else {
                uint32_t pk[8] = {
                    (uint32_t)wreg[0].x, (uint32_t)wreg[0].y, (uint32_t)wreg[0].z, (uint32_t)wreg[0].w,
                    (uint32_t)wreg[1].x, (uint32_t)wreg[1].y, (uint32_t)wreg[1].z, (uint32_t)wreg[1].w };
                #pragma unroll
                for (int j = 0; j < 8; j++) dq4(pk[j], s2, c1152, o[2 * j], o[2 * j + 1]);
            }
            uint32_t off = (uint32_t)rr * 128 + (uint32_t)hh * 64;
            STS128(wfp + swz(off),      o[0],  o[1],  o[2],  o[3]);
            STS128(wfp + swz(off + 16), o[4],  o[5],  o[6],  o[7]);
            STS128(wfp + swz(off + 32), o[8],  o[9],  o[10], o[11]);
            STS128(wfp + swz(off + 48), o[12], o[13], o[14], o[15]);
        }

        // ---- refill W regs (1 chunk ahead) + X prefetch ----
        if (i + 1 < NCHUNK) loadW(i + 1);
        if (i + SPREF < NCHUNK) issueX(i + SPREF, wr);
        cpa_commit();
        __syncthreads();                         // Wfp visible

        // ---- A fragments + MMA ----
        #pragma unroll
        for (int kt = 0; kt < 4; kt++)
            #pragma unroll
            for (int mt = 0; mt < 2; mt++) {
                uint32_t afr[4];
                int row = mr * 32 + mt * 16 + ((t & 1) << 3) + (lane & 7);
                int cb  = kt * 32 + ((t >> 1) << 4);
                ldsm4(afr, wfp + swz(row * 128 + cb));
                #pragma unroll
                for (int nt = 0; nt < 4; nt++)
                    mma16816(acc[mt][nt], afr, bfr[kt][nt * 2], bfr[kt][nt * 2 + 1]);
            }

        rd = (rd == NX - 1) ? 0 : rd + 1;
        wr = (wr == NX - 1) ? 0 : wr + 1;
    }

    // ---- epilogue ----
    const int olo = row0 + mr * 32 + (lane >> 2);
    #pragma unroll
    for (int mt = 0; mt < 2; mt++) {
        int o0 = olo + mt * 16;
        float b0 = g_badd[o0], b8 = g_badd[o0 + 8];
        #pragma unroll
        for (int nt = 0; nt < 4; nt++) {
            int bc = nc * 32 + nt * 8 + (lane & 3) * 2;
            out[(size_t)bc * OUTF + o0]           = acc[mt][nt][0] + b0;
            out[(size_t)(bc + 1) * OUTF + o0]     = acc[mt][nt][1] + b0;
            out[(size_t)bc * OUTF + o0 + 8]       = acc[mt][nt][2] + b8;
            out[(size_t)(bc + 1) * OUTF + o0 + 8] = acc[mt][nt][3] + b8;
        }
    }
}

__global__ void __launch_bounds__(256, 1)
gemm_kernel(const void* __restrict__ Wv, float* __restrict__ out) {
    // uniform per-CTA dtype check on 256B of W (L2-resident after first CTA)
    const int* wi = (const int*)Wv;
    bool i32 = true;
    #pragma unroll 8
    for (int i = 0; i < 64; i++) { int q = wi[i]; i32 &= (q >= -127 && q <= 127); }
    if (i32) gemm_body<1>((const char*)Wv, out);
    else     gemm_body<0>((const char*)Wv, out);
}

// ---------------- launch ----------------
extern "C" void kernel_launch(void* const* d_in, const int* in_sizes, int n_in,
                              void* d_out, int out_size) {
    const void* x = nullptr; const void* wq = nullptr; const void* scale = nullptr;
    const void* bias = nullptr; const void* wres = nullptr;
    for (int i = 0; i < n_in; i++) {
        long long n = in_sizes[i];
        if (n == (long long)BATCH * INF)     x = d_in[i];
        else if (n == (long long)OUTF * INF) wq = d_in[i];
        else if (n == (long long)OUTF * NG)  scale = d_in[i];
        else if (n == OUTF) { if (!bias) bias = d_in[i]; else wres = d_in[i]; }
    }
    if (!x || !wq || !scale || !bias || !wres) {
        if (n_in >= 5) {
            x = d_in[0]; wq = d_in[1]; scale = d_in[2]; bias = d_in[3]; wres = d_in[4];
        } else return;
    }
    float* out = (float*)d_out;

    prolog_kernel<<<512, 256>>>((const float*)x, scale, bias, wres);

    (void)cudaFuncSetAttribute(gemm_kernel,
                               cudaFuncAttributeMaxDynamicSharedMemorySize, SMEM_GEMM);
    gemm_kernel<<<NBLK, 256, SMEM_GEMM>>>(wq, out);
}

// round 9
// speedup vs baseline: 1.3296x; 1.3296x over previous
#include <cuda_runtime.h>
#include <cuda_fp16.h>
#include <cstdint>

// ---------------- problem constants ----------------
#define OUTF  11008
#define INF   4096
#define BATCH 64
#define NG    32              // 4096/128 quant groups
#define MTILE 64              // weight rows per CTA
#define KC    64              // K per chunk
#define NCHUNK 64
#define NBLK  (OUTF / MTILE)  // 172 CTAs

// rings
#define NX    4               // X slots (8KB each)
#define NW    3               // W raw slots
#define SPREF 3               // prefetch distance, wait_group(SPREF-1)
#define WROW  272             // padded raw W row stride (bank-conflict-free)

// smem layout from 1KB-aligned base
#define SC_OFF  0                            // 4KB scales (64 rows x 32 groups fp16)
#define X_OFF   4096                         // 4 x 8192 = 32768
#define WR_OFF  (X_OFF + NX * 8192)          // 36864; 3 x 17408 = 52224
#define WF_OFF  (WR_OFF + NW * 64 * WROW)    // 89088; 2 x 8192
#define SMEM_GEMM (WF_OFF + 2 * 8192 + 1024) // 106496

// ---------------- device globals ----------------
__device__ __half2 g_x16[BATCH * INF / 2];
__device__ __half  g_sc16[OUTF * NG];
__device__ float   g_badd[OUTF];

// ---------------- helpers ----------------
static __device__ __forceinline__ uint32_t smem_u32(const void* p) {
    uint32_t a;
    asm("{ .reg .u64 t; cvta.to.shared.u64 t, %1; cvt.u32.u64 %0, t; }" : "=r"(a) : "l"(p));
    return a;
}
static __device__ __forceinline__ uint32_t swz(uint32_t off) {
    return off ^ ((off >> 3) & 0x70);
}
static __device__ __forceinline__ void cpa16(uint32_t dst, const void* src) {
    asm volatile("cp.async.cg.shared.global [%0], [%1], 16;" :: "r"(dst), "l"(src));
}
static __device__ __forceinline__ void cpa_commit() {
    asm volatile("cp.async.commit_group;" ::: "memory");
}
static __device__ __forceinline__ void ldsm4(uint32_t* r, uint32_t addr) {
    asm volatile("ldmatrix.sync.aligned.m8n8.x4.shared.b16 {%0,%1,%2,%3}, [%4];"
        : "=r"(r[0]), "=r"(r[1]), "=r"(r[2]), "=r"(r[3]) : "r"(addr));
}
static __device__ __forceinline__ void mma16816(float* d, const uint32_t* a,
                                                uint32_t b0, uint32_t b1) {
    asm volatile("mma.sync.aligned.m16n8k16.row.col.f32.f16.f16.f32 "
        "{%0,%1,%2,%3}, {%4,%5,%6,%7}, {%8,%9}, {%0,%1,%2,%3};"
        : "+f"(d[0]), "+f"(d[1]), "+f"(d[2]), "+f"(d[3])
        : "r"(a[0]), "r"(a[1]), "r"(a[2]), "r"(a[3]), "r"(b0), "r"(b1));
}
static __device__ __forceinline__ __half2 u32_as_h2(uint32_t u) {
    __half2 h; *reinterpret_cast<uint32_t*>(&h) = u; return h;
}
static __device__ __forceinline__ uint32_t h2_as_u32(__half2 h) {
    return *reinterpret_cast<uint32_t*>(&h);
}

#define LDS128(r0, r1, r2, r3, addr) \
    asm volatile("ld.shared.v4.u32 {%0, %1, %2, %3}, [%4];" \
        : "=r"(r0), "=r"(r1), "=r"(r2), "=r"(r3) : "r"(addr))
#define STS128(addr, r0, r1, r2, r3) \
    asm volatile("st.shared.v4.b32 [%0], {%1, %2, %3, %4};" \
        :: "r"(addr), "r"(r0), "r"(r1), "r"(r2), "r"(r3) : "memory")

// 4 int8 bytes (packed u32) -> 2 half2, times s2 (exact PRMT 0x6400 trick)
static __device__ __forceinline__ void dq4(uint32_t packed, __half2 s2, __half2 c1152,
                                           uint32_t& o0, uint32_t& o1) {
    uint32_t v  = packed ^ 0x80808080u;
    uint32_t lo = __byte_perm(v, 0x64646464u, 0x4140);
    uint32_t hi = __byte_perm(v, 0x64646464u, 0x4342);
    o0 = h2_as_u32(__hmul2(__hsub2(u32_as_h2(lo), c1152), s2));
    o1 = h2_as_u32(__hmul2(__hsub2(u32_as_h2(hi), c1152), s2));
}

static __device__ __forceinline__ float read_mode16(const void* p, int i, int mode) {
    if (mode == 1) {
        unsigned short u = reinterpret_cast<const unsigned short*>(p)[i];
        return __uint_as_float(((unsigned)u) << 16);
    } else if (mode == 0) {
        return __half2float(reinterpret_cast<const __half*>(p)[i]);
    }
    return reinterpret_cast<const float*>(p)[i];
}

// ---------------- fused prolog: x->fp16, scale->fp16, bias+res->f32 ----------------
__global__ void prolog_kernel(const float* __restrict__ x,
                              const void* __restrict__ s,
                              const void* __restrict__ b,
                              const void* __restrict__ r) {
    const int idx = blockIdx.x * 256 + threadIdx.x;   // 512*256 = 131072

    float2 v = reinterpret_cast<const float2*>(x)[idx];
    g_x16[idx] = __floats2half2_rn(v.x, v.y);

    // per-block scale dtype detection (256B, L2-resident after first block)
    bool bf = true, fh = true;
    const unsigned* su = (const unsigned*)s;
    #pragma unroll 8
    for (int i = 0; i < 64; i++) {
        unsigned w = su[i];
        #pragma unroll
        for (int h = 0; h < 2; h++) {
            unsigned u = (h ? (w >> 16) : w) & 0xFFFFu;
            float ab = __uint_as_float(u << 16);
            float af = __half2float(__ushort_as_half((unsigned short)u));
            bf &= (ab > 5e-5f && ab < 0.02f);
            fh &= (af > 5e-5f && af < 0.02f);
        }
    }
    const int m = bf ? 1 : (fh ? 0 : 2);

    for (int i = idx; i < OUTF * NG; i += 512 * 256)
        g_sc16[i] = __float2half(read_mode16(s, i, m));
    if (idx < OUTF)
        g_badd[idx] = read_mode16(b, idx, m) + read_mode16(r, idx, m);
}

// ---------------- unified GEMM body (WMODE: 1 = int32 weights, 0 = int8) --------
template <int WMODE>
static __device__ __forceinline__ void gemm_body(const char* __restrict__ Wb,
                                                 float* __restrict__ out) {
    extern __shared__ char smem_raw[];
    uint32_t sb = (smem_u32(smem_raw) + 1023) & ~1023u;
    const int tid = threadIdx.x, lane = tid & 31, wid = tid >> 5;
    const int mr = wid & 1, nc = wid >> 1;     // 2 row-groups x 4 col-groups
    const int t = lane >> 3;
    const int row0 = blockIdx.x * MTILE;
    const char* xb = (const char*)g_x16;
    const uint32_t SC = sb, X0 = sb + X_OFF, WR = sb + WR_OFF, WFP = sb + WF_OFF;

    auto issueX = [&](int p, int slot) {
        uint32_t xsl = X0 + slot * 8192;
        const int k0 = p * KC;
        #pragma unroll
        for (int j = 0; j < 2; j++) {
            int c = tid + j * 256, r = c >> 3, q = c & 7;
            cpa16(xsl + swz(r * 128 + q * 16),
                  xb + (size_t)r * (INF * 2) + (size_t)k0 * 2 + q * 16);
        }
    };
    auto issueW = [&](int p, int slot) {
        uint32_t wsl = WR + slot * (64 * WROW);
        const int k0 = p * KC;
        if (WMODE) {
            #pragma unroll
            for (int j = 0; j < 4; j++) {      // 64 rows x 256B
                int c = tid + j * 256, r = c >> 4, q = c & 15;
                cpa16(wsl + r * WROW + q * 16,
                      Wb + ((size_t)(row0 + r) * INF + k0 + q * 4) * 4);
            }
        } else {
            int r = tid >> 2, q = tid & 3;     // 64 rows x 64B
            cpa16(wsl + r * WROW + q * 16,
                  Wb + (size_t)(row0 + r) * INF + k0 + q * 16);
        }
    };

    {   // prologue: scales + chunks 0..2
        const char* scb = (const char*)g_sc16 + (size_t)row0 * NG * 2;
        cpa16(SC + tid * 16, scb + tid * 16);  // 256 x 16B = 4KB
        issueX(0, 0); issueW(0, 0); cpa_commit();
        issueX(1, 1); issueW(1, 1); cpa_commit();
        issueX(2, 2); issueW(2, 2); cpa_commit();
    }

    const __half2 c1152 = __half2half2(__ushort_as_half((unsigned short)0x6480));
    float acc[2][2][4] = {};
    const int rr = tid & 63, hh = tid >> 6;    // dequant ownership: 16 vals/thread
    int w3 = 0;                                 // i % 3

    for (int i = 0; i < NCHUNK; i++) {
        asm volatile("cp.async.wait_group %0;" :: "n"(SPREF - 1) : "memory");
        __syncthreads();                        // chunk i (X + W raw) visible

        const uint32_t xsl = X0 + (i & 3) * 8192;
        const uint32_t wsl = WR + w3 * (64 * WROW);
        const uint32_t wfp = WFP + (i & 1) * 8192;

        // ---- B fragments (16 cols per warp) ----
        uint32_t bfr[4][4];
        #pragma unroll
        for (int kt = 0; kt < 4; kt++) {
            int n  = nc * 16 + ((t >> 1) << 3) + (lane & 7);
            int cb = kt * 32 + ((t & 1) << 4);
            ldsm4(bfr[kt], xsl + swz(n * 128 + cb));
        }

        // ---- dequant raw W -> Wfp ----
        {
            const int g = i >> 1;
            unsigned short sv;
            asm volatile("ld.shared.u16 %0, [%1];" : "=h"(sv)
                : "r"(SC + (uint32_t)(rr * NG + g) * 2) : "memory");
            __half2 s2 = __half2half2(__ushort_as_half(sv));
            uint32_t o[8];
            if (WMODE) {
                #pragma unroll
                for (int k = 0; k < 4; k++) {
                    uint32_t a0, a1, a2, a3;
                    LDS128(a0, a1, a2, a3, wsl + rr * WROW + hh * 64 + k * 16);
                    uint32_t t01 = __byte_perm(a0, a1, 0x0040);
                    uint32_t t23 = __byte_perm(a2, a3, 0x0040);
                    dq4(__byte_perm(t01, t23, 0x5410), s2, c1152, o[2*k], o[2*k+1]);
                }
            } else {
                uint32_t a0, a1, a2, a3;
                LDS128(a0, a1, a2, a3, wsl + rr * WROW + hh * 16);
                dq4(a0, s2, c1152, o[0], o[1]);
                dq4(a1, s2, c1152, o[2], o[3]);
                dq4(a2, s2, c1152, o[4], o[5]);
                dq4(a3, s2, c1152, o[6], o[7]);
            }
            uint32_t off = (uint32_t)rr * 128 + (uint32_t)hh * 32;
            STS128(wfp + swz(off),      o[0], o[1], o[2], o[3]);
            STS128(wfp + swz(off + 16), o[4], o[5], o[6], o[7]);
        }

        __syncthreads();   // all reads of slot i done; Wfp visible

        // ---- prefetch chunk i+3 (W reuses slot w3, now fully consumed) ----
        if (i + SPREF < NCHUNK) {
            issueX(i + SPREF, (i + SPREF) & 3);
            issueW(i + SPREF, w3);
        }
        cpa_commit();

        // ---- A fragments + MMA ----
        #pragma unroll
        for (int kt = 0; kt < 4; kt++)
            #pragma unroll
            for (int mt = 0; mt < 2; mt++) {
                uint32_t afr[4];
                int row = mr * 32 + mt * 16 + ((t & 1) << 3) + (lane & 7);
                int cb  = kt * 32 + ((t >> 1) << 4);
                ldsm4(afr, wfp + swz(row * 128 + cb));
                #pragma unroll
                for (int nt = 0; nt < 2; nt++)
                    mma16816(acc[mt][nt], afr, bfr[kt][nt * 2], bfr[kt][nt * 2 + 1]);
            }

        w3 = (w3 == NW - 1) ? 0 : w3 + 1;
    }

    // ---- epilogue ----
    const int olo = row0 + mr * 32 + (lane >> 2);
    #pragma unroll
    for (int mt = 0; mt < 2; mt++) {
        int o0 = olo + mt * 16;
        float b0 = g_badd[o0], b8 = g_badd[o0 + 8];
        #pragma unroll
        for (int nt = 0; nt < 2; nt++) {
            int bc = nc * 16 + nt * 8 + (lane & 3) * 2;
            out[(size_t)bc * OUTF + o0]           = acc[mt][nt][0] + b0;
            out[(size_t)(bc + 1) * OUTF + o0]     = acc[mt][nt][1] + b0;
            out[(size_t)bc * OUTF + o0 + 8]       = acc[mt][nt][2] + b8;
            out[(size_t)(bc + 1) * OUTF + o0 + 8] = acc[mt][nt][3] + b8;
        }
    }
}

__global__ void __launch_bounds__(256, 2)
gemm_kernel(const void* __restrict__ Wv, float* __restrict__ out) {
    const int* wi = (const int*)Wv;           // uniform dtype check on 256B of W
    bool i32 = true;
    #pragma unroll 8
    for (int i = 0; i < 64; i++) { int q = wi[i]; i32 &= (q >= -127 && q <= 127); }
    if (i32) gemm_body<1>((const char*)Wv, out);
    else     gemm_body<0>((const char*)Wv, out);
}

// ---------------- launch ----------------
extern "C" void kernel_launch(void* const* d_in, const int* in_sizes, int n_in,
                              void* d_out, int out_size) {
    const void* x = nullptr; const void* wq = nullptr; const void* scale = nullptr;
    const void* bias = nullptr; const void* wres = nullptr;
    for (int i = 0; i < n_in; i++) {
        long long n = in_sizes[i];
        if (n == (long long)BATCH * INF)     x = d_in[i];
        else if (n == (long long)OUTF * INF) wq = d_in[i];
        else if (n == (long long)OUTF * NG)  scale = d_in[i];
        else if (n == OUTF) { if (!bias) bias = d_in[i]; else wres = d_in[i]; }
    }
    if (!x || !wq || !scale || !bias || !wres) {
        if (n_in >= 5) {
            x = d_in[0]; wq = d_in[1]; scale = d_in[2]; bias = d_in[3]; wres = d_in[4];
        } else return;
    }
    float* out = (float*)d_out;

    prolog_kernel<<<512, 256>>>((const float*)x, scale, bias, wres);

    (void)cudaFuncSetAttribute(gemm_kernel,
                               cudaFuncAttributeMaxDynamicSharedMemorySize, SMEM_GEMM);
    gemm_kernel<<<NBLK, 256, SMEM_GEMM>>>(wq, out);
}